// round 2
// baseline (speedup 1.0000x reference)
#include <cuda_runtime.h>
#include <math.h>

#define FULLMASK 0xffffffffu

constexpr int Bb = 8;
constexpr int Nn = 7168;
constexpr int Uu = 49152;
constexpr float SCALE = 0.125f;   // 1/sqrt(64)

// ---------------- scratch (__device__ globals; no allocation) ----------------
__device__ float g_Mcat[64 * 256];    // [k][g*64+c] = scale * sum_j Wq[k][g16+j]*Wk[c][g16+j]
__device__ float g_biasM[256];        // [g*64+c]    = scale * sum_j bq[g16+j]*Wk[c][g16+j]
__device__ float g_z0[Bb * Nn * 64];  // attention output (pre-LN), 14.7 MB

// ---------------- K0: fold Wq/Wk/bq into Mcat/biasM ----------------
__global__ void k0_precompute(const float* __restrict__ Wq,
                              const float* __restrict__ Wk,
                              const float* __restrict__ bq)
{
    int oc = threadIdx.x;        // 256 threads, one output column each
    int g = oc >> 6, c = oc & 63;
    const float* wk = Wk + c * 64 + g * 16;
    float bacc = 0.f;
#pragma unroll
    for (int j = 0; j < 16; ++j) bacc += bq[g * 16 + j] * wk[j];
    g_biasM[oc] = SCALE * bacc;
    for (int k = 0; k < 64; ++k) {
        float s = 0.f;
#pragma unroll
        for (int j = 0; j < 16; ++j) s += Wq[k * 64 + g * 16 + j] * wk[j];
        g_Mcat[k * 256 + oc] = SCALE * s;
    }
}

// ---------------- K2: fused attention per bunch ----------------
// Block = 256 threads = 8 warps, handles 32 consecutive x-tokens of one bunch.
// TO = u tokens per x token; U0/U1 = u part base offsets (tokens, per batch).
template <int TO, int NBASE, int NB, int U0, int U1>
__global__ __launch_bounds__(256) void k2_attn(const float* __restrict__ u,
                                               const float* __restrict__ x,
                                               const float* __restrict__ Wv,
                                               const float* __restrict__ bv)
{
    __shared__ float s_x[32 * 68];    // x tile
    __shared__ float s_w[32 * 260];   // wqk [tok][g*64+c], later reused for ubar
    __shared__ float s_sc[8][64];     // per-warp scores [t*4+g]

    const int tid = threadIdx.x;
    constexpr int TPB = NB / 32;
    const int b = blockIdx.x / TPB;
    const int tile = blockIdx.x % TPB;
    const int m0 = tile * 32;                // local token base within bunch

    // ---- load x tile ----
    {
        int tok = tid >> 3, c0 = (tid & 7) * 8;
        const float* xp = x + ((size_t)(b * Nn + NBASE + m0 + tok)) * 64 + c0;
        *(float4*)&s_x[tok * 68 + c0]     = *(const float4*)xp;
        *(float4*)&s_x[tok * 68 + c0 + 4] = *(const float4*)(xp + 4);
    }
    __syncthreads();

    // ---- phase 1: wqk = X @ Mcat + biasM  (each thread: 4 tokens x 8 cols) ----
    {
        const int cb = (tid & 31) * 8;
        const int tokg = tid >> 5;
        float acc[4][8];
        float4 b0 = *(const float4*)(g_biasM + cb);
        float4 b1 = *(const float4*)(g_biasM + cb + 4);
        float bb[8] = {b0.x, b0.y, b0.z, b0.w, b1.x, b1.y, b1.z, b1.w};
#pragma unroll
        for (int i = 0; i < 4; ++i)
#pragma unroll
            for (int j = 0; j < 8; ++j) acc[i][j] = bb[j];
#pragma unroll 4
        for (int k = 0; k < 64; ++k) {
            float4 w0 = *(const float4*)(g_Mcat + k * 256 + cb);
            float4 w1 = *(const float4*)(g_Mcat + k * 256 + cb + 4);
            float wv[8] = {w0.x, w0.y, w0.z, w0.w, w1.x, w1.y, w1.z, w1.w};
#pragma unroll
            for (int i = 0; i < 4; ++i) {
                float a = s_x[(tokg * 4 + i) * 68 + k];
#pragma unroll
                for (int j = 0; j < 8; ++j) acc[i][j] += a * wv[j];
            }
        }
#pragma unroll
        for (int i = 0; i < 4; ++i) {
            float* dst = &s_w[(tokg * 4 + i) * 260 + cb];
            *(float4*)dst       = make_float4(acc[i][0], acc[i][1], acc[i][2], acc[i][3]);
            *(float4*)(dst + 4) = make_float4(acc[i][4], acc[i][5], acc[i][6], acc[i][7]);
        }
    }
    __syncthreads();

    // ---- phase 2/3: stream u, scores -> softmax -> ubar (warp per token) ----
    const int w = tid >> 5, lane = tid & 31;
#pragma unroll 1
    for (int i = 0; i < 4; ++i) {
        const int tok = w * 4 + i;
        const int m = m0 + tok;
        const long ubase = (m < NB / 2) ? (U0 + (long)m * TO)
                                        : (U1 + (long)(m - NB / 2) * TO);
        const float* up = u + ((size_t)b * Uu + ubase) * 64;
        float uu0[TO], uu1[TO];
#pragma unroll
        for (int t = 0; t < TO; ++t) {
            uu0[t] = up[t * 64 + lane];
            uu1[t] = up[t * 64 + lane + 32];
        }
        const float* wq = &s_w[tok * 260];
#pragma unroll
        for (int t = 0; t < TO; ++t) {
            float p0 = uu0[t] * wq[lane]        + uu1[t] * wq[lane + 32];
            float p1 = uu0[t] * wq[64 + lane]   + uu1[t] * wq[96 + lane];
            float p2 = uu0[t] * wq[128 + lane]  + uu1[t] * wq[160 + lane];
            float p3 = uu0[t] * wq[192 + lane]  + uu1[t] * wq[224 + lane];
#pragma unroll
            for (int off = 16; off; off >>= 1) {
                p0 += __shfl_xor_sync(FULLMASK, p0, off);
                p1 += __shfl_xor_sync(FULLMASK, p1, off);
                p2 += __shfl_xor_sync(FULLMASK, p2, off);
                p3 += __shfl_xor_sync(FULLMASK, p3, off);
            }
            if (lane < 4) {
                float sv = (lane == 0) ? p0 : (lane == 1) ? p1 : (lane == 2) ? p2 : p3;
                s_sc[w][t * 4 + lane] = sv;
            }
        }
        __syncwarp();
        float ub_lo[4], ub_hi[4];
#pragma unroll
        for (int g = 0; g < 4; ++g) {
            float mx = -1e30f;
#pragma unroll
            for (int t = 0; t < TO; ++t) mx = fmaxf(mx, s_sc[w][t * 4 + g]);
            float d = 0.f, alo = 0.f, ahi = 0.f;
#pragma unroll
            for (int t = 0; t < TO; ++t) {
                float e = __expf(s_sc[w][t * 4 + g] - mx);
                d += e;
                alo += e * uu0[t];
                ahi += e * uu1[t];
            }
            float inv = __frcp_rn(d);
            ub_lo[g] = alo * inv;
            ub_hi[g] = ahi * inv;
        }
        __syncwarp();
        float* wd = &s_w[tok * 260];
#pragma unroll
        for (int g = 0; g < 4; ++g) {
            wd[g * 64 + lane]      = ub_lo[g];
            wd[g * 64 + lane + 32] = ub_hi[g];
        }
    }
    __syncthreads();

    // ---- phase 4: out = ubar_g @ Wv_g + bv  (each thread: 4 tokens x 2 cols) ----
    {
        const int tokg = tid >> 5;   // warp id = token group
        const int c0 = lane * 2;     // output cols [c0, c0+1], same group
        const int g = c0 >> 4;
        float acc0[4] = {0.f, 0.f, 0.f, 0.f};
        float acc1[4] = {0.f, 0.f, 0.f, 0.f};
#pragma unroll 4
        for (int k = 0; k < 64; ++k) {
            float2 wv = *(const float2*)(Wv + k * 64 + c0);
#pragma unroll
            for (int i = 0; i < 4; ++i) {
                float a = s_w[(tokg * 4 + i) * 260 + g * 64 + k];
                acc0[i] += a * wv.x;
                acc1[i] += a * wv.y;
            }
        }
        float2 bvv = *(const float2*)(bv + c0);
#pragma unroll
        for (int i = 0; i < 4; ++i) {
            int n = NBASE + m0 + tokg * 4 + i;
            float2 o = make_float2(acc0[i] + bvv.x, acc1[i] + bvv.y);
            *(float2*)&g_z0[((size_t)(b * Nn + n)) * 64 + c0] = o;
        }
    }
}

// ---------------- K3: LN1 -> MLP(gelu) -> LN2 + shortcut ----------------
__global__ __launch_bounds__(256) void k3_mlp(const float* __restrict__ x,
                                              const float* __restrict__ g1,
                                              const float* __restrict__ be1,
                                              const float* __restrict__ Wm1,
                                              const float* __restrict__ bm1,
                                              const float* __restrict__ Wm2,
                                              const float* __restrict__ bm2,
                                              const float* __restrict__ g2,
                                              const float* __restrict__ be2,
                                              const float* __restrict__ Ws,
                                              const float* __restrict__ bs,
                                              float* __restrict__ out)
{
    __shared__ float s_z[32 * 68];    // LN1 out, later z2
    __shared__ float s_h[32 * 260];   // hidden (32x256), later [Xs | Sc]

    const int tid = threadIdx.x, lane = tid & 31, w = tid >> 5;
    const size_t base = (size_t)blockIdx.x * 32;   // flat token index in B*N

    // ---- load z0 tile ----
    {
        int tok = tid >> 3, c0 = (tid & 7) * 8;
        const float* zp = g_z0 + (base + tok) * 64 + c0;
        *(float4*)&s_z[tok * 68 + c0]     = *(const float4*)zp;
        *(float4*)&s_z[tok * 68 + c0 + 4] = *(const float4*)(zp + 4);
    }
    __syncthreads();

    // ---- LN1 in place (warp per 4 tokens) ----
#pragma unroll
    for (int i = 0; i < 4; ++i) {
        int tok = w * 4 + i;
        float v0 = s_z[tok * 68 + lane], v1 = s_z[tok * 68 + lane + 32];
        float s1 = v0 + v1, s2 = v0 * v0 + v1 * v1;
#pragma unroll
        for (int off = 16; off; off >>= 1) {
            s1 += __shfl_xor_sync(FULLMASK, s1, off);
            s2 += __shfl_xor_sync(FULLMASK, s2, off);
        }
        float m = s1 * (1.f / 64.f);
        float var = s2 * (1.f / 64.f) - m * m;
        float r = rsqrtf(var + 1e-5f);
        s_z[tok * 68 + lane]      = (v0 - m) * r * g1[lane] + be1[lane];
        s_z[tok * 68 + lane + 32] = (v1 - m) * r * g1[lane + 32] + be1[lane + 32];
    }
    __syncthreads();

    // ---- GEMM1 + exact gelu: H = gelu(Z @ Wm1 + bm1) ----
    {
        const int cb = (tid & 31) * 8;
        const int tokg = tid >> 5;
        float acc[4][8];
        float4 b0 = *(const float4*)(bm1 + cb);
        float4 b1 = *(const float4*)(bm1 + cb + 4);
        float bb[8] = {b0.x, b0.y, b0.z, b0.w, b1.x, b1.y, b1.z, b1.w};
#pragma unroll
        for (int i = 0; i < 4; ++i)
#pragma unroll
            for (int j = 0; j < 8; ++j) acc[i][j] = bb[j];
#pragma unroll 4
        for (int k = 0; k < 64; ++k) {
            float4 w0 = *(const float4*)(Wm1 + k * 256 + cb);
            float4 w1 = *(const float4*)(Wm1 + k * 256 + cb + 4);
            float wv[8] = {w0.x, w0.y, w0.z, w0.w, w1.x, w1.y, w1.z, w1.w};
#pragma unroll
            for (int i = 0; i < 4; ++i) {
                float a = s_z[(tokg * 4 + i) * 68 + k];
#pragma unroll
                for (int j = 0; j < 8; ++j) acc[i][j] += a * wv[j];
            }
        }
#pragma unroll
        for (int i = 0; i < 4; ++i) {
            float o[8];
#pragma unroll
            for (int j = 0; j < 8; ++j) {
                float v = acc[i][j];
                o[j] = 0.5f * v * (1.f + erff(v * 0.70710678118654752f));
            }
            float* dst = &s_h[(tokg * 4 + i) * 260 + cb];
            *(float4*)dst       = make_float4(o[0], o[1], o[2], o[3]);
            *(float4*)(dst + 4) = make_float4(o[4], o[5], o[6], o[7]);
        }
    }
    __syncthreads();

    // ---- GEMM2 (k-split x4): z2 = H @ Wm2 + bm2 -> s_z ----
    const int ksec = tid >> 6;
    const int t64 = tid & 63;
    const int tokg2 = t64 >> 3;      // 8 token groups x 4 tokens
    const int cb2 = (t64 & 7) * 8;   // 8 col groups x 8 cols
    {
        float a2[4][8];
#pragma unroll
        for (int i = 0; i < 4; ++i)
#pragma unroll
            for (int j = 0; j < 8; ++j) a2[i][j] = 0.f;
#pragma unroll 4
        for (int k = ksec * 64; k < ksec * 64 + 64; ++k) {
            float4 w0 = *(const float4*)(Wm2 + k * 64 + cb2);
            float4 w1 = *(const float4*)(Wm2 + k * 64 + cb2 + 4);
            float wv[8] = {w0.x, w0.y, w0.z, w0.w, w1.x, w1.y, w1.z, w1.w};
#pragma unroll
            for (int i = 0; i < 4; ++i) {
                float a = s_h[(tokg2 * 4 + i) * 260 + k];
#pragma unroll
                for (int j = 0; j < 8; ++j) a2[i][j] += a * wv[j];
            }
        }
        for (int r = 0; r < 4; ++r) {
            if (ksec == r) {
#pragma unroll
                for (int i = 0; i < 4; ++i)
#pragma unroll
                    for (int j = 0; j < 8; ++j) {
                        float* dst = &s_z[(tokg2 * 4 + i) * 68 + cb2 + j];
                        if (r == 0) *dst = a2[i][j] + bm2[cb2 + j];
                        else        *dst += a2[i][j];
                    }
            }
            __syncthreads();
        }
    }

    // ---- load x tile into Xs = s_h[0..2176) ----
    {
        int tok = tid >> 3, c0 = (tid & 7) * 8;
        const float* xp = x + (base + tok) * 64 + c0;
        *(float4*)&s_h[tok * 68 + c0]     = *(const float4*)xp;
        *(float4*)&s_h[tok * 68 + c0 + 4] = *(const float4*)(xp + 4);
    }
    __syncthreads();

    // ---- shortcut GEMM (k-split x4): Sc = X @ Ws + bs -> s_h[2176..) ----
    {
        float a3[4][8];
#pragma unroll
        for (int i = 0; i < 4; ++i)
#pragma unroll
            for (int j = 0; j < 8; ++j) a3[i][j] = 0.f;
#pragma unroll 4
        for (int k = ksec * 16; k < ksec * 16 + 16; ++k) {
            float4 w0 = *(const float4*)(Ws + k * 64 + cb2);
            float4 w1 = *(const float4*)(Ws + k * 64 + cb2 + 4);
            float wv[8] = {w0.x, w0.y, w0.z, w0.w, w1.x, w1.y, w1.z, w1.w};
#pragma unroll
            for (int i = 0; i < 4; ++i) {
                float a = s_h[(tokg2 * 4 + i) * 68 + k];
#pragma unroll
                for (int j = 0; j < 8; ++j) a3[i][j] += a * wv[j];
            }
        }
        for (int r = 0; r < 4; ++r) {
            if (ksec == r) {
#pragma unroll
                for (int i = 0; i < 4; ++i)
#pragma unroll
                    for (int j = 0; j < 8; ++j) {
                        float* dst = &s_h[2176 + (tokg2 * 4 + i) * 68 + cb2 + j];
                        if (r == 0) *dst = a3[i][j] + bs[cb2 + j];
                        else        *dst += a3[i][j];
                    }
            }
            __syncthreads();
        }
    }

    // ---- LN2 + shortcut -> out ----
#pragma unroll
    for (int i = 0; i < 4; ++i) {
        int tok = w * 4 + i;
        float v0 = s_z[tok * 68 + lane], v1 = s_z[tok * 68 + lane + 32];
        float s1 = v0 + v1, s2 = v0 * v0 + v1 * v1;
#pragma unroll
        for (int off = 16; off; off >>= 1) {
            s1 += __shfl_xor_sync(FULLMASK, s1, off);
            s2 += __shfl_xor_sync(FULLMASK, s2, off);
        }
        float m = s1 * (1.f / 64.f);
        float var = s2 * (1.f / 64.f) - m * m;
        float r = rsqrtf(var + 1e-5f);
        float o0 = (v0 - m) * r * g2[lane]      + be2[lane]      + s_h[2176 + tok * 68 + lane];
        float o1 = (v1 - m) * r * g2[lane + 32] + be2[lane + 32] + s_h[2176 + tok * 68 + lane + 32];
        out[(base + tok) * 64 + lane]      = o0;
        out[(base + tok) * 64 + lane + 32] = o1;
    }
}

// ---------------- launch ----------------
extern "C" void kernel_launch(void* const* d_in, const int* in_sizes, int n_in,
                              void* d_out, int out_size)
{
    const float* u   = (const float*)d_in[0];
    const float* x   = (const float*)d_in[1];
    const float* Wk  = (const float*)d_in[2];
    // d_in[3] = bk: cancels in softmax, unused
    const float* Wq  = (const float*)d_in[4];
    const float* bq  = (const float*)d_in[5];
    const float* Wv  = (const float*)d_in[6];
    const float* bv  = (const float*)d_in[7];
    const float* g1  = (const float*)d_in[8];
    const float* be1 = (const float*)d_in[9];
    const float* Wm1 = (const float*)d_in[10];
    const float* bm1 = (const float*)d_in[11];
    const float* Wm2 = (const float*)d_in[12];
    const float* bm2 = (const float*)d_in[13];
    const float* g2  = (const float*)d_in[14];
    const float* be2 = (const float*)d_in[15];
    const float* Ws  = (const float*)d_in[16];
    const float* bs  = (const float*)d_in[17];
    float* out = (float*)d_out;

    k0_precompute<<<1, 256>>>(Wq, Wk, bq);
    // bunch 0: n=4096, to=4, u parts at 0 / 24576
    k2_attn<4, 0, 4096, 0, 24576><<<Bb * (4096 / 32), 256>>>(u, x, Wv, bv);
    // bunch 1: n=2048, to=8, u parts at 8192 / 32768
    k2_attn<8, 4096, 2048, 8192, 32768><<<Bb * (2048 / 32), 256>>>(u, x, Wv, bv);
    // bunch 2: n=1024, to=16, u parts at 16384 / 40960
    k2_attn<16, 6144, 1024, 16384, 40960><<<Bb * (1024 / 32), 256>>>(u, x, Wv, bv);
    // MLP + shortcut
    k3_mlp<<<(Bb * Nn) / 32, 256>>>(x, g1, be1, Wm1, bm1, Wm2, bm2,
                                    g2, be2, Ws, bs, out);
    (void)in_sizes; (void)n_in; (void)out_size;
}

// round 5
// speedup vs baseline: 1.1285x; 1.1285x over previous
#include <cuda_runtime.h>
#include <math.h>

#define FULLMASK 0xffffffffu

constexpr int Bb = 8;
constexpr int Nn = 7168;
constexpr int Uu = 49152;
constexpr int TILES_PER_B = Nn / 32;   // 224
constexpr float SCALE = 0.125f;        // 1/sqrt(64)

// ---------------- persistent folded weights (no allocation) ----------------
__device__ float g_Mcat[64 * 256];    // [k][g*64+c] = scale * sum_j Wq[k][g16+j]*Wk[c][g16+j]
__device__ float g_biasM[256];        // [g*64+c]    = scale * sum_j bq[g16+j]*Wk[c][g16+j]

// ---------------- K0: fold Wq/Wk/bq into Mcat/biasM ----------------
__global__ void k0_precompute(const float* __restrict__ Wq,
                              const float* __restrict__ Wk,
                              const float* __restrict__ bq)
{
    int oc = threadIdx.x;        // 256 threads, one output column each
    int g = oc >> 6, c = oc & 63;
    const float* wk = Wk + c * 64 + g * 16;
    float bacc = 0.f;
#pragma unroll
    for (int j = 0; j < 16; ++j) bacc += bq[g * 16 + j] * wk[j];
    g_biasM[oc] = SCALE * bacc;
    for (int k = 0; k < 64; ++k) {
        float s = 0.f;
#pragma unroll
        for (int j = 0; j < 16; ++j) s += Wq[k * 64 + g * 16 + j] * wk[j];
        g_Mcat[k * 256 + oc] = SCALE * s;
    }
}

// ---------------- attention part (templated on TO) ----------------
// s_z: 32*68 floats (holds x tile, then z0 result)
// s_w: 32*260 floats (wqk, then ubar)
// s_sc: [8][64] per-warp score scratch
template <int TO>
__device__ __forceinline__ void attn_part(const float* __restrict__ u,
                                          const float* __restrict__ x,
                                          const float* __restrict__ Wv,
                                          const float* __restrict__ bv,
                                          int b, int nglob0, int m0,
                                          int NBhalf, int U0, int U1,
                                          float* s_z, float* s_w,
                                          float (*s_sc)[64])
{
    const int tid = threadIdx.x;

    // ---- load x tile into s_z ----
    {
        int tok = tid >> 3, c0 = (tid & 7) * 8;
        const float* xp = x + ((size_t)(b * Nn + nglob0 + tok)) * 64 + c0;
        *(float4*)&s_z[tok * 68 + c0]     = *(const float4*)xp;
        *(float4*)&s_z[tok * 68 + c0 + 4] = *(const float4*)(xp + 4);
    }
    __syncthreads();

    // ---- phase 1: wqk = X @ Mcat + biasM  (4 tokens x 8 cols per thread) ----
    {
        const int cb = (tid & 31) * 8;
        const int tokg = tid >> 5;
        float acc[4][8];
        float4 b0 = *(const float4*)(g_biasM + cb);
        float4 b1 = *(const float4*)(g_biasM + cb + 4);
        float bb[8] = {b0.x, b0.y, b0.z, b0.w, b1.x, b1.y, b1.z, b1.w};
#pragma unroll
        for (int i = 0; i < 4; ++i)
#pragma unroll
            for (int j = 0; j < 8; ++j) acc[i][j] = bb[j];
#pragma unroll 4
        for (int k = 0; k < 64; ++k) {
            float4 w0 = *(const float4*)(g_Mcat + k * 256 + cb);
            float4 w1 = *(const float4*)(g_Mcat + k * 256 + cb + 4);
            float wv[8] = {w0.x, w0.y, w0.z, w0.w, w1.x, w1.y, w1.z, w1.w};
#pragma unroll
            for (int i = 0; i < 4; ++i) {
                float a = s_z[(tokg * 4 + i) * 68 + k];
#pragma unroll
                for (int j = 0; j < 8; ++j) acc[i][j] += a * wv[j];
            }
        }
#pragma unroll
        for (int i = 0; i < 4; ++i) {
            float* dst = &s_w[(tokg * 4 + i) * 260 + cb];
            *(float4*)dst       = make_float4(acc[i][0], acc[i][1], acc[i][2], acc[i][3]);
            *(float4*)(dst + 4) = make_float4(acc[i][4], acc[i][5], acc[i][6], acc[i][7]);
        }
    }
    __syncthreads();

    // ---- phase 2/3: stream u, scores -> softmax -> ubar (warp per token) ----
    const int w = tid >> 5, lane = tid & 31;
#pragma unroll 1
    for (int i = 0; i < 4; ++i) {
        const int tok = w * 4 + i;
        const int m = m0 + tok;
        const long ubase = (m < NBhalf) ? ((long)U0 + (long)m * TO)
                                        : ((long)U1 + (long)(m - NBhalf) * TO);
        const float* up = u + ((size_t)b * Uu + ubase) * 64;
        float uu0[TO], uu1[TO];
#pragma unroll
        for (int t = 0; t < TO; ++t) {
            uu0[t] = up[t * 64 + lane];
            uu1[t] = up[t * 64 + lane + 32];
        }
        const float* wq = &s_w[tok * 260];
#pragma unroll
        for (int t = 0; t < TO; ++t) {
            float p0 = uu0[t] * wq[lane]        + uu1[t] * wq[lane + 32];
            float p1 = uu0[t] * wq[64 + lane]   + uu1[t] * wq[96 + lane];
            float p2 = uu0[t] * wq[128 + lane]  + uu1[t] * wq[160 + lane];
            float p3 = uu0[t] * wq[192 + lane]  + uu1[t] * wq[224 + lane];
#pragma unroll
            for (int off = 16; off; off >>= 1) {
                p0 += __shfl_xor_sync(FULLMASK, p0, off);
                p1 += __shfl_xor_sync(FULLMASK, p1, off);
                p2 += __shfl_xor_sync(FULLMASK, p2, off);
                p3 += __shfl_xor_sync(FULLMASK, p3, off);
            }
            if (lane < 4) {
                float sv = (lane == 0) ? p0 : (lane == 1) ? p1 : (lane == 2) ? p2 : p3;
                s_sc[w][t * 4 + lane] = sv;
            }
        }
        __syncwarp();

        // ---- exp once per (t,g) pair + warp denominator, normalize in smem ----
        if (TO == 4) {
            int p = lane & 15;                       // (t = p>>2, g = p&3); hi-lanes duplicate
            float e = __expf(s_sc[w][p]);
            float d = e;
            d += __shfl_xor_sync(FULLMASK, d, 4);
            d += __shfl_xor_sync(FULLMASK, d, 8);
            s_sc[w][p] = e * __frcp_rn(d);
        } else if (TO == 8) {
            int p = lane;                            // 32 pairs
            float e = __expf(s_sc[w][p]);
            float d = e;
            d += __shfl_xor_sync(FULLMASK, d, 4);
            d += __shfl_xor_sync(FULLMASK, d, 8);
            d += __shfl_xor_sync(FULLMASK, d, 16);
            s_sc[w][p] = e * __frcp_rn(d);
        } else {                                     // TO == 16: 64 pairs, 2 per lane (same g)
            float e1 = __expf(s_sc[w][lane]);
            float e2 = __expf(s_sc[w][lane + 32]);
            float d = e1 + e2;
            d += __shfl_xor_sync(FULLMASK, d, 4);
            d += __shfl_xor_sync(FULLMASK, d, 8);
            d += __shfl_xor_sync(FULLMASK, d, 16);
            float inv = __frcp_rn(d);
            s_sc[w][lane]      = e1 * inv;
            s_sc[w][lane + 32] = e2 * inv;
        }
        __syncwarp();

        // ---- accumulate ubar (weights broadcast from smem) ----
        float ub_lo[4], ub_hi[4];
#pragma unroll
        for (int g = 0; g < 4; ++g) {
            float alo = 0.f, ahi = 0.f;
#pragma unroll
            for (int t = 0; t < TO; ++t) {
                float e = s_sc[w][t * 4 + g];
                alo += e * uu0[t];
                ahi += e * uu1[t];
            }
            ub_lo[g] = alo;
            ub_hi[g] = ahi;
        }
        __syncwarp();     // s_sc reads done before next iteration overwrites
        float* wd = &s_w[tok * 260];
#pragma unroll
        for (int g = 0; g < 4; ++g) {
            wd[g * 64 + lane]      = ub_lo[g];
            wd[g * 64 + lane + 32] = ub_hi[g];
        }
    }
    __syncthreads();

    // ---- phase 4: z0 = ubar_g @ Wv_g + bv -> s_z ----
    {
        const int tokg = tid >> 5;
        const int c0 = (tid & 31) * 2;
        const int g = c0 >> 4;
        float acc0[4] = {0.f, 0.f, 0.f, 0.f};
        float acc1[4] = {0.f, 0.f, 0.f, 0.f};
#pragma unroll 4
        for (int k = 0; k < 64; ++k) {
            float2 wv = *(const float2*)(Wv + k * 64 + c0);
#pragma unroll
            for (int i = 0; i < 4; ++i) {
                float a = s_w[(tokg * 4 + i) * 260 + g * 64 + k];
                acc0[i] += a * wv.x;
                acc1[i] += a * wv.y;
            }
        }
        float2 bvv = *(const float2*)(bv + c0);
#pragma unroll
        for (int i = 0; i < 4; ++i) {
            *(float2*)&s_z[(tokg * 4 + i) * 68 + c0] =
                make_float2(acc0[i] + bvv.x, acc1[i] + bvv.y);
        }
    }
    __syncthreads();
}

// ---------------- fused kernel: attention + LN1 + MLP + LN2 + shortcut ----------------
__global__ __launch_bounds__(256) void fuse_all(const float* __restrict__ u,
                                                const float* __restrict__ x,
                                                const float* __restrict__ Wv,
                                                const float* __restrict__ bv,
                                                const float* __restrict__ g1,
                                                const float* __restrict__ be1,
                                                const float* __restrict__ Wm1,
                                                const float* __restrict__ bm1,
                                                const float* __restrict__ Wm2,
                                                const float* __restrict__ bm2,
                                                const float* __restrict__ g2,
                                                const float* __restrict__ be2,
                                                const float* __restrict__ Ws,
                                                const float* __restrict__ bs,
                                                float* __restrict__ out)
{
    __shared__ float s_z[32 * 68];      // x tile -> z0 -> LN1 -> z2
    __shared__ float s_h[32 * 260];     // wqk/ubar -> hidden -> [Xs | Sc]
    __shared__ float s_sc[8][64];

    const int tid = threadIdx.x, lane = tid & 31, w = tid >> 5;
    const int tix = blockIdx.x;
    const int b = tix / TILES_PER_B;
    const int r = tix % TILES_PER_B;

    int nglob0;
    if (r < 128) {
        nglob0 = r * 32;
        attn_part<4>(u, x, Wv, bv, b, nglob0, r * 32, 2048, 0, 24576, s_z, s_h, s_sc);
    } else if (r < 192) {
        nglob0 = 4096 + (r - 128) * 32;
        attn_part<8>(u, x, Wv, bv, b, nglob0, (r - 128) * 32, 1024, 8192, 32768, s_z, s_h, s_sc);
    } else {
        nglob0 = 6144 + (r - 192) * 32;
        attn_part<16>(u, x, Wv, bv, b, nglob0, (r - 192) * 32, 512, 16384, 40960, s_z, s_h, s_sc);
    }

    const size_t base = (size_t)b * Nn + nglob0;

    // ---- LN1 in place on s_z (warp per 4 tokens) ----
#pragma unroll
    for (int i = 0; i < 4; ++i) {
        int tok = w * 4 + i;
        float v0 = s_z[tok * 68 + lane], v1 = s_z[tok * 68 + lane + 32];
        float s1 = v0 + v1, s2 = v0 * v0 + v1 * v1;
#pragma unroll
        for (int off = 16; off; off >>= 1) {
            s1 += __shfl_xor_sync(FULLMASK, s1, off);
            s2 += __shfl_xor_sync(FULLMASK, s2, off);
        }
        float m = s1 * (1.f / 64.f);
        float var = s2 * (1.f / 64.f) - m * m;
        float rr = rsqrtf(var + 1e-5f);
        s_z[tok * 68 + lane]      = (v0 - m) * rr * g1[lane] + be1[lane];
        s_z[tok * 68 + lane + 32] = (v1 - m) * rr * g1[lane + 32] + be1[lane + 32];
    }
    __syncthreads();

    // ---- GEMM1 + exact gelu: H = gelu(Z @ Wm1 + bm1) -> s_h ----
    {
        const int cb = (tid & 31) * 8;
        const int tokg = tid >> 5;
        float acc[4][8];
        float4 b0 = *(const float4*)(bm1 + cb);
        float4 b1 = *(const float4*)(bm1 + cb + 4);
        float bb[8] = {b0.x, b0.y, b0.z, b0.w, b1.x, b1.y, b1.z, b1.w};
#pragma unroll
        for (int i = 0; i < 4; ++i)
#pragma unroll
            for (int j = 0; j < 8; ++j) acc[i][j] = bb[j];
#pragma unroll 4
        for (int k = 0; k < 64; ++k) {
            float4 w0 = *(const float4*)(Wm1 + k * 256 + cb);
            float4 w1 = *(const float4*)(Wm1 + k * 256 + cb + 4);
            float wv[8] = {w0.x, w0.y, w0.z, w0.w, w1.x, w1.y, w1.z, w1.w};
#pragma unroll
            for (int i = 0; i < 4; ++i) {
                float a = s_z[(tokg * 4 + i) * 68 + k];
#pragma unroll
                for (int j = 0; j < 8; ++j) acc[i][j] += a * wv[j];
            }
        }
#pragma unroll
        for (int i = 0; i < 4; ++i) {
            float o[8];
#pragma unroll
            for (int j = 0; j < 8; ++j) {
                float v = acc[i][j];
                o[j] = 0.5f * v * (1.f + erff(v * 0.70710678118654752f));
            }
            float* dst = &s_h[(tokg * 4 + i) * 260 + cb];
            *(float4*)dst       = make_float4(o[0], o[1], o[2], o[3]);
            *(float4*)(dst + 4) = make_float4(o[4], o[5], o[6], o[7]);
        }
    }
    __syncthreads();

    // ---- GEMM2 (k-split x4): z2 = H @ Wm2 + bm2 -> s_z ----
    const int ksec = tid >> 6;
    const int t64 = tid & 63;
    const int tokg2 = t64 >> 3;
    const int cb2 = (t64 & 7) * 8;
    {
        float a2[4][8];
#pragma unroll
        for (int i = 0; i < 4; ++i)
#pragma unroll
            for (int j = 0; j < 8; ++j) a2[i][j] = 0.f;
#pragma unroll 4
        for (int k = ksec * 64; k < ksec * 64 + 64; ++k) {
            float4 w0 = *(const float4*)(Wm2 + k * 64 + cb2);
            float4 w1 = *(const float4*)(Wm2 + k * 64 + cb2 + 4);
            float wv[8] = {w0.x, w0.y, w0.z, w0.w, w1.x, w1.y, w1.z, w1.w};
#pragma unroll
            for (int i = 0; i < 4; ++i) {
                float a = s_h[(tokg2 * 4 + i) * 260 + k];
#pragma unroll
                for (int j = 0; j < 8; ++j) a2[i][j] += a * wv[j];
            }
        }
        for (int rr = 0; rr < 4; ++rr) {
            if (ksec == rr) {
#pragma unroll
                for (int i = 0; i < 4; ++i)
#pragma unroll
                    for (int j = 0; j < 8; ++j) {
                        float* dst = &s_z[(tokg2 * 4 + i) * 68 + cb2 + j];
                        if (rr == 0) *dst = a2[i][j] + bm2[cb2 + j];
                        else         *dst += a2[i][j];
                    }
            }
            __syncthreads();
        }
    }

    // ---- load x tile into s_h[0..2176) ----
    {
        int tok = tid >> 3, c0 = (tid & 7) * 8;
        const float* xp = x + (base + tok) * 64 + c0;
        *(float4*)&s_h[tok * 68 + c0]     = *(const float4*)xp;
        *(float4*)&s_h[tok * 68 + c0 + 4] = *(const float4*)(xp + 4);
    }
    __syncthreads();

    // ---- shortcut GEMM (k-split x4): Sc = X @ Ws + bs -> s_h[2176..) ----
    {
        float a3[4][8];
#pragma unroll
        for (int i = 0; i < 4; ++i)
#pragma unroll
            for (int j = 0; j < 8; ++j) a3[i][j] = 0.f;
#pragma unroll 4
        for (int k = ksec * 16; k < ksec * 16 + 16; ++k) {
            float4 w0 = *(const float4*)(Ws + k * 64 + cb2);
            float4 w1 = *(const float4*)(Ws + k * 64 + cb2 + 4);
            float wv[8] = {w0.x, w0.y, w0.z, w0.w, w1.x, w1.y, w1.z, w1.w};
#pragma unroll
            for (int i = 0; i < 4; ++i) {
                float a = s_h[(tokg2 * 4 + i) * 68 + k];
#pragma unroll
                for (int j = 0; j < 8; ++j) a3[i][j] += a * wv[j];
            }
        }
        for (int rr = 0; rr < 4; ++rr) {
            if (ksec == rr) {
#pragma unroll
                for (int i = 0; i < 4; ++i)
#pragma unroll
                    for (int j = 0; j < 8; ++j) {
                        float* dst = &s_h[2176 + (tokg2 * 4 + i) * 68 + cb2 + j];
                        if (rr == 0) *dst = a3[i][j] + bs[cb2 + j];
                        else         *dst += a3[i][j];
                    }
            }
            __syncthreads();
        }
    }

    // ---- LN2 + shortcut -> out ----
#pragma unroll
    for (int i = 0; i < 4; ++i) {
        int tok = w * 4 + i;
        float v0 = s_z[tok * 68 + lane], v1 = s_z[tok * 68 + lane + 32];
        float s1 = v0 + v1, s2 = v0 * v0 + v1 * v1;
#pragma unroll
        for (int off = 16; off; off >>= 1) {
            s1 += __shfl_xor_sync(FULLMASK, s1, off);
            s2 += __shfl_xor_sync(FULLMASK, s2, off);
        }
        float m = s1 * (1.f / 64.f);
        float var = s2 * (1.f / 64.f) - m * m;
        float rr = rsqrtf(var + 1e-5f);
        float o0 = (v0 - m) * rr * g2[lane]      + be2[lane]      + s_h[2176 + tok * 68 + lane];
        float o1 = (v1 - m) * rr * g2[lane + 32] + be2[lane + 32] + s_h[2176 + tok * 68 + lane + 32];
        out[(base + tok) * 64 + lane]      = o0;
        out[(base + tok) * 64 + lane + 32] = o1;
    }
}

// ---------------- launch ----------------
extern "C" void kernel_launch(void* const* d_in, const int* in_sizes, int n_in,
                              void* d_out, int out_size)
{
    const float* u   = (const float*)d_in[0];
    const float* x   = (const float*)d_in[1];
    const float* Wk  = (const float*)d_in[2];
    // d_in[3] = bk: constant over u-tokens -> cancels in softmax, unused
    const float* Wq  = (const float*)d_in[4];
    const float* bq  = (const float*)d_in[5];
    const float* Wv  = (const float*)d_in[6];
    const float* bv  = (const float*)d_in[7];
    const float* g1  = (const float*)d_in[8];
    const float* be1 = (const float*)d_in[9];
    const float* Wm1 = (const float*)d_in[10];
    const float* bm1 = (const float*)d_in[11];
    const float* Wm2 = (const float*)d_in[12];
    const float* bm2 = (const float*)d_in[13];
    const float* g2  = (const float*)d_in[14];
    const float* be2 = (const float*)d_in[15];
    const float* Ws  = (const float*)d_in[16];
    const float* bs  = (const float*)d_in[17];
    float* out = (float*)d_out;

    k0_precompute<<<1, 256>>>(Wq, Wk, bq);
    fuse_all<<<Bb * TILES_PER_B, 256>>>(u, x, Wv, bv, g1, be1, Wm1, bm1,
                                        Wm2, bm2, g2, be2, Ws, bs, out);
    (void)in_sizes; (void)n_in; (void)out_size;
}

// round 7
// speedup vs baseline: 1.2422x; 1.1008x over previous
#include <cuda_runtime.h>
#include <math.h>

#define FULLMASK 0xffffffffu

constexpr int Bb = 8;
constexpr int Nn = 7168;
constexpr int Uu = 49152;
constexpr int TILES_PER_B = Nn / 32;   // 224
constexpr float SCALE = 0.125f;        // 1/sqrt(64)

// ---------------- packed f32x2 helpers ----------------
__device__ __forceinline__ unsigned long long pack2(float a) {
    unsigned long long r;
    asm("mov.b64 %0, {%1, %1};" : "=l"(r) : "f"(a));
    return r;
}
__device__ __forceinline__ void ffma2(unsigned long long& acc,
                                      unsigned long long a, unsigned long long w) {
    asm("fma.rn.f32x2 %0, %1, %2, %0;" : "+l"(acc) : "l"(a), "l"(w));
}
__device__ __forceinline__ float2 u2f(unsigned long long v) {
    float2 r;
    asm("mov.b64 {%0, %1}, %2;" : "=f"(r.x), "=f"(r.y) : "l"(v));
    return r;
}

// ---------------- persistent folded weights (no allocation) ----------------
__device__ float g_Mcat[64 * 256];    // [k][g*64+c] = scale * sum_j Wq[k][g16+j]*Wk[c][g16+j]
__device__ float g_biasM[256];        // [g*64+c]    = scale * sum_j bq[g16+j]*Wk[c][g16+j]

// ---------------- K0: fold Wq/Wk/bq into Mcat/biasM ----------------
__global__ void k0_precompute(const float* __restrict__ Wq,
                              const float* __restrict__ Wk,
                              const float* __restrict__ bq)
{
    int oc = threadIdx.x;        // 256 threads, one output column each
    int g = oc >> 6, c = oc & 63;
    const float* wk = Wk + c * 64 + g * 16;
    float bacc = 0.f;
#pragma unroll
    for (int j = 0; j < 16; ++j) bacc += bq[g * 16 + j] * wk[j];
    g_biasM[oc] = SCALE * bacc;
    for (int k = 0; k < 64; ++k) {
        float s = 0.f;
#pragma unroll
        for (int j = 0; j < 16; ++j) s += Wq[k * 64 + g * 16 + j] * wk[j];
        g_Mcat[k * 256 + oc] = SCALE * s;
    }
}

// ---- generic 32x64 @ 64xNC register-tiled GEMM step (4 tok x 8 cols / thread),
//      activations from smem (stride SA), weights row-major NC cols, f32x2 pipe ----
template <int SA, int NC>
__device__ __forceinline__ void gemm_acc(const float* __restrict__ W,
                                         const float* sA, int tokg, int cb,
                                         unsigned long long (&acc)[4][4])
{
#pragma unroll 2
    for (int k4 = 0; k4 < 64; k4 += 4) {
        float4 av[4];
#pragma unroll
        for (int i = 0; i < 4; ++i)
            av[i] = *(const float4*)&sA[(tokg * 4 + i) * SA + k4];
#pragma unroll
        for (int kk = 0; kk < 4; ++kk) {
            const float* wp = W + (k4 + kk) * NC + cb;
            ulonglong2 w0 = *(const ulonglong2*)wp;
            ulonglong2 w1 = *(const ulonglong2*)(wp + 4);
#pragma unroll
            for (int i = 0; i < 4; ++i) {
                float a = (kk == 0) ? av[i].x : (kk == 1) ? av[i].y
                         : (kk == 2) ? av[i].z : av[i].w;
                unsigned long long a2 = pack2(a);
                ffma2(acc[i][0], a2, w0.x);
                ffma2(acc[i][1], a2, w0.y);
                ffma2(acc[i][2], a2, w1.x);
                ffma2(acc[i][3], a2, w1.y);
            }
        }
    }
}

// ---------------- attention part (templated on TO) ----------------
template <int TO>
__device__ __forceinline__ void attn_part(const float* __restrict__ u,
                                          const float* __restrict__ x,
                                          const float* __restrict__ Wv,
                                          const float* __restrict__ bv,
                                          int b, int nglob0, int m0,
                                          int NBhalf, int U0, int U1,
                                          float* s_z, float* s_w,
                                          float (*s_sc)[64])
{
    const int tid = threadIdx.x;

    // ---- load x tile into s_z ----
    {
        int tok = tid >> 3, c0 = (tid & 7) * 8;
        const float* xp = x + ((size_t)(b * Nn + nglob0 + tok)) * 64 + c0;
        *(float4*)&s_z[tok * 68 + c0]     = *(const float4*)xp;
        *(float4*)&s_z[tok * 68 + c0 + 4] = *(const float4*)(xp + 4);
    }
    __syncthreads();

    // ---- phase 1: wqk = X @ Mcat + biasM ----
    {
        const int cb = (tid & 31) * 8;
        const int tokg = tid >> 5;
        unsigned long long acc[4][4];
        ulonglong2 bb0 = *(const ulonglong2*)(g_biasM + cb);
        ulonglong2 bb1 = *(const ulonglong2*)(g_biasM + cb + 4);
#pragma unroll
        for (int i = 0; i < 4; ++i) {
            acc[i][0] = bb0.x; acc[i][1] = bb0.y;
            acc[i][2] = bb1.x; acc[i][3] = bb1.y;
        }
        gemm_acc<68, 256>(g_Mcat, s_z, tokg, cb, acc);
#pragma unroll
        for (int i = 0; i < 4; ++i) {
            float2 r0 = u2f(acc[i][0]), r1 = u2f(acc[i][1]);
            float2 r2 = u2f(acc[i][2]), r3 = u2f(acc[i][3]);
            float* dst = &s_w[(tokg * 4 + i) * 260 + cb];
            *(float4*)dst       = make_float4(r0.x, r0.y, r1.x, r1.y);
            *(float4*)(dst + 4) = make_float4(r2.x, r2.y, r3.x, r3.y);
        }
    }
    __syncthreads();

    // ---- phase 2/3: stream u, scores -> softmax -> ubar (warp per token) ----
    const int w = tid >> 5, lane = tid & 31;
    const bool b0 = (lane & 1), b1 = (lane & 2);
#pragma unroll 1
    for (int i = 0; i < 4; ++i) {
        const int tok = w * 4 + i;
        const int m = m0 + tok;
        const long ubase = (m < NBhalf) ? ((long)U0 + (long)m * TO)
                                        : ((long)U1 + (long)(m - NBhalf) * TO);
        const float* up = u + ((size_t)b * Uu + ubase) * 64;
        float uu0[TO], uu1[TO];
#pragma unroll
        for (int t = 0; t < TO; ++t) {
            uu0[t] = up[t * 64 + lane];
            uu1[t] = up[t * 64 + lane + 32];
        }
        const float* wq = &s_w[tok * 260];
#pragma unroll
        for (int t = 0; t < TO; ++t) {
            float p0 = uu0[t] * wq[lane]        + uu1[t] * wq[lane + 32];
            float p1 = uu0[t] * wq[64 + lane]   + uu1[t] * wq[96 + lane];
            float p2 = uu0[t] * wq[128 + lane]  + uu1[t] * wq[160 + lane];
            float p3 = uu0[t] * wq[192 + lane]  + uu1[t] * wq[224 + lane];
            // 6-shuffle 4-group reduction: lane&3 == g ends holding group g sum
            float tA = __shfl_xor_sync(FULLMASK, b0 ? p0 : p1, 1);
            float va = (b0 ? p1 : p0) + tA;
            float tB = __shfl_xor_sync(FULLMASK, b0 ? p2 : p3, 1);
            float vb = (b0 ? p3 : p2) + tB;
            float tC = __shfl_xor_sync(FULLMASK, b1 ? va : vb, 2);
            float c  = (b1 ? vb : va) + tC;
            c += __shfl_xor_sync(FULLMASK, c, 4);
            c += __shfl_xor_sync(FULLMASK, c, 8);
            c += __shfl_xor_sync(FULLMASK, c, 16);
            if (lane < 4) s_sc[w][t * 4 + lane] = c;
        }
        __syncwarp();

        // ---- exp once per (t,g) pair + warp denominator, normalize in smem ----
        if (TO == 4) {
            int p = lane & 15;
            float e = __expf(s_sc[w][p]);
            float d = e;
            d += __shfl_xor_sync(FULLMASK, d, 4);
            d += __shfl_xor_sync(FULLMASK, d, 8);
            s_sc[w][p] = e * __frcp_rn(d);
        } else if (TO == 8) {
            int p = lane;
            float e = __expf(s_sc[w][p]);
            float d = e;
            d += __shfl_xor_sync(FULLMASK, d, 4);
            d += __shfl_xor_sync(FULLMASK, d, 8);
            d += __shfl_xor_sync(FULLMASK, d, 16);
            s_sc[w][p] = e * __frcp_rn(d);
        } else {
            float e1 = __expf(s_sc[w][lane]);
            float e2 = __expf(s_sc[w][lane + 32]);
            float d = e1 + e2;
            d += __shfl_xor_sync(FULLMASK, d, 4);
            d += __shfl_xor_sync(FULLMASK, d, 8);
            d += __shfl_xor_sync(FULLMASK, d, 16);
            float inv = __frcp_rn(d);
            s_sc[w][lane]      = e1 * inv;
            s_sc[w][lane + 32] = e2 * inv;
        }
        __syncwarp();

        // ---- accumulate ubar (weights broadcast from smem) ----
        float ub_lo[4], ub_hi[4];
#pragma unroll
        for (int g = 0; g < 4; ++g) {
            float alo = 0.f, ahi = 0.f;
#pragma unroll
            for (int t = 0; t < TO; ++t) {
                float e = s_sc[w][t * 4 + g];
                alo += e * uu0[t];
                ahi += e * uu1[t];
            }
            ub_lo[g] = alo;
            ub_hi[g] = ahi;
        }
        __syncwarp();
        float* wd = &s_w[tok * 260];
#pragma unroll
        for (int g = 0; g < 4; ++g) {
            wd[g * 64 + lane]      = ub_lo[g];
            wd[g * 64 + lane + 32] = ub_hi[g];
        }
    }
    __syncthreads();

    // ---- phase 4: z0 = ubar_g @ Wv_g + bv -> s_z ----
    {
        const int tokg = tid >> 5;
        const int c0 = (tid & 31) * 2;
        const int g = c0 >> 4;
        unsigned long long acc[4] = {0ull, 0ull, 0ull, 0ull};
#pragma unroll 2
        for (int k4 = 0; k4 < 64; k4 += 4) {
            float4 av[4];
#pragma unroll
            for (int i = 0; i < 4; ++i)
                av[i] = *(const float4*)&s_w[(tokg * 4 + i) * 260 + g * 64 + k4];
#pragma unroll
            for (int kk = 0; kk < 4; ++kk) {
                unsigned long long wv = *(const unsigned long long*)(Wv + (k4 + kk) * 64 + c0);
#pragma unroll
                for (int i = 0; i < 4; ++i) {
                    float a = (kk == 0) ? av[i].x : (kk == 1) ? av[i].y
                             : (kk == 2) ? av[i].z : av[i].w;
                    ffma2(acc[i], pack2(a), wv);
                }
            }
        }
        float2 bvv = *(const float2*)(bv + c0);
#pragma unroll
        for (int i = 0; i < 4; ++i) {
            float2 v = u2f(acc[i]);
            *(float2*)&s_z[(tokg * 4 + i) * 68 + c0] =
                make_float2(v.x + bvv.x, v.y + bvv.y);
        }
    }
    __syncthreads();
}

// ---------------- fused kernel: attention + LN1 + MLP + LN2 + shortcut ----------------
__global__ __launch_bounds__(256) void fuse_all(const float* __restrict__ u,
                                                const float* __restrict__ x,
                                                const float* __restrict__ Wv,
                                                const float* __restrict__ bv,
                                                const float* __restrict__ g1,
                                                const float* __restrict__ be1,
                                                const float* __restrict__ Wm1,
                                                const float* __restrict__ bm1,
                                                const float* __restrict__ Wm2,
                                                const float* __restrict__ bm2,
                                                const float* __restrict__ g2,
                                                const float* __restrict__ be2,
                                                const float* __restrict__ Ws,
                                                const float* __restrict__ bs,
                                                float* __restrict__ out)
{
    __shared__ float s_z[32 * 68];      // x tile -> z0 -> LN1 -> z2
    __shared__ float s_h[32 * 260];     // wqk/ubar -> hidden -> [Xs | Sc]
    __shared__ float s_sc[8][64];

    const int tid = threadIdx.x, lane = tid & 31, w = tid >> 5;
    const int tix = blockIdx.x;
    const int b = tix / TILES_PER_B;
    const int r = tix % TILES_PER_B;

    int nglob0;
    if (r < 128) {
        nglob0 = r * 32;
        attn_part<4>(u, x, Wv, bv, b, nglob0, r * 32, 2048, 0, 24576, s_z, s_h, s_sc);
    } else if (r < 192) {
        nglob0 = 4096 + (r - 128) * 32;
        attn_part<8>(u, x, Wv, bv, b, nglob0, (r - 128) * 32, 1024, 8192, 32768, s_z, s_h, s_sc);
    } else {
        nglob0 = 6144 + (r - 192) * 32;
        attn_part<16>(u, x, Wv, bv, b, nglob0, (r - 192) * 32, 512, 16384, 40960, s_z, s_h, s_sc);
    }

    const size_t base = (size_t)b * Nn + nglob0;

    // ---- LN1 in place on s_z (warp per 4 tokens) ----
#pragma unroll
    for (int i = 0; i < 4; ++i) {
        int tok = w * 4 + i;
        float v0 = s_z[tok * 68 + lane], v1 = s_z[tok * 68 + lane + 32];
        float s1 = v0 + v1, s2 = v0 * v0 + v1 * v1;
#pragma unroll
        for (int off = 16; off; off >>= 1) {
            s1 += __shfl_xor_sync(FULLMASK, s1, off);
            s2 += __shfl_xor_sync(FULLMASK, s2, off);
        }
        float m = s1 * (1.f / 64.f);
        float var = s2 * (1.f / 64.f) - m * m;
        float rr = rsqrtf(var + 1e-5f);
        s_z[tok * 68 + lane]      = (v0 - m) * rr * g1[lane] + be1[lane];
        s_z[tok * 68 + lane + 32] = (v1 - m) * rr * g1[lane + 32] + be1[lane + 32];
    }
    __syncthreads();

    // ---- GEMM1 + exact gelu: H = gelu(Z @ Wm1 + bm1) -> s_h ----
    {
        const int cb = (tid & 31) * 8;
        const int tokg = tid >> 5;
        unsigned long long acc[4][4];
        ulonglong2 bb0 = *(const ulonglong2*)(bm1 + cb);
        ulonglong2 bb1 = *(const ulonglong2*)(bm1 + cb + 4);
#pragma unroll
        for (int i = 0; i < 4; ++i) {
            acc[i][0] = bb0.x; acc[i][1] = bb0.y;
            acc[i][2] = bb1.x; acc[i][3] = bb1.y;
        }
        gemm_acc<68, 256>(Wm1, s_z, tokg, cb, acc);
#pragma unroll
        for (int i = 0; i < 4; ++i) {
            float vv[8];
            float2 r0 = u2f(acc[i][0]), r1 = u2f(acc[i][1]);
            float2 r2 = u2f(acc[i][2]), r3 = u2f(acc[i][3]);
            vv[0] = r0.x; vv[1] = r0.y; vv[2] = r1.x; vv[3] = r1.y;
            vv[4] = r2.x; vv[5] = r2.y; vv[6] = r3.x; vv[7] = r3.y;
            float o[8];
#pragma unroll
            for (int j = 0; j < 8; ++j)
                o[j] = 0.5f * vv[j] * (1.f + erff(vv[j] * 0.70710678118654752f));
            float* dst = &s_h[(tokg * 4 + i) * 260 + cb];
            *(float4*)dst       = make_float4(o[0], o[1], o[2], o[3]);
            *(float4*)(dst + 4) = make_float4(o[4], o[5], o[6], o[7]);
        }
    }
    __syncthreads();

    // ---- GEMM2 (k-split x4): z2 = H @ Wm2 + bm2 -> s_z ----
    const int ksec = tid >> 6;
    const int t64 = tid & 63;
    const int tokg2 = t64 >> 3;
    const int cb2 = (t64 & 7) * 8;
    {
        unsigned long long a2[4][4];
#pragma unroll
        for (int i = 0; i < 4; ++i)
#pragma unroll
            for (int j = 0; j < 4; ++j) a2[i][j] = 0ull;
#pragma unroll 2
        for (int k4 = ksec * 64; k4 < ksec * 64 + 64; k4 += 4) {
            float4 av[4];
#pragma unroll
            for (int i = 0; i < 4; ++i)
                av[i] = *(const float4*)&s_h[(tokg2 * 4 + i) * 260 + k4];
#pragma unroll
            for (int kk = 0; kk < 4; ++kk) {
                const float* wp = Wm2 + (k4 + kk) * 64 + cb2;
                ulonglong2 w0 = *(const ulonglong2*)wp;
                ulonglong2 w1 = *(const ulonglong2*)(wp + 4);
#pragma unroll
                for (int i = 0; i < 4; ++i) {
                    float a = (kk == 0) ? av[i].x : (kk == 1) ? av[i].y
                             : (kk == 2) ? av[i].z : av[i].w;
                    unsigned long long ap = pack2(a);
                    ffma2(a2[i][0], ap, w0.x);
                    ffma2(a2[i][1], ap, w0.y);
                    ffma2(a2[i][2], ap, w1.x);
                    ffma2(a2[i][3], ap, w1.y);
                }
            }
        }
        for (int rr = 0; rr < 4; ++rr) {
            if (ksec == rr) {
#pragma unroll
                for (int i = 0; i < 4; ++i)
#pragma unroll
                    for (int j = 0; j < 4; ++j) {
                        float2 v = u2f(a2[i][j]);
                        float2* dst = (float2*)&s_z[(tokg2 * 4 + i) * 68 + cb2 + j * 2];
                        if (rr == 0) {
                            float2 bm = *(const float2*)(bm2 + cb2 + j * 2);
                            *dst = make_float2(v.x + bm.x, v.y + bm.y);
                        } else {
                            float2 old = *dst;
                            *dst = make_float2(old.x + v.x, old.y + v.y);
                        }
                    }
            }
            __syncthreads();
        }
    }

    // ---- load x tile into s_h[0..2176) ----
    {
        int tok = tid >> 3, c0 = (tid & 7) * 8;
        const float* xp = x + (base + tok) * 64 + c0;
        *(float4*)&s_h[tok * 68 + c0]     = *(const float4*)xp;
        *(float4*)&s_h[tok * 68 + c0 + 4] = *(const float4*)(xp + 4);
    }
    __syncthreads();

    // ---- shortcut GEMM (k-split x4): Sc = X @ Ws + bs -> s_h[2176..) ----
    {
        unsigned long long a3[4][4];
#pragma unroll
        for (int i = 0; i < 4; ++i)
#pragma unroll
            for (int j = 0; j < 4; ++j) a3[i][j] = 0ull;
#pragma unroll
        for (int k4 = ksec * 16; k4 < ksec * 16 + 16; k4 += 4) {
            float4 av[4];
#pragma unroll
            for (int i = 0; i < 4; ++i)
                av[i] = *(const float4*)&s_h[(tokg2 * 4 + i) * 68 + k4];
#pragma unroll
            for (int kk = 0; kk < 4; ++kk) {
                const float* wp = Ws + (k4 + kk) * 64 + cb2;
                ulonglong2 w0 = *(const ulonglong2*)wp;
                ulonglong2 w1 = *(const ulonglong2*)(wp + 4);
#pragma unroll
                for (int i = 0; i < 4; ++i) {
                    float a = (kk == 0) ? av[i].x : (kk == 1) ? av[i].y
                             : (kk == 2) ? av[i].z : av[i].w;
                    unsigned long long ap = pack2(a);
                    ffma2(a3[i][0], ap, w0.x);
                    ffma2(a3[i][1], ap, w0.y);
                    ffma2(a3[i][2], ap, w1.x);
                    ffma2(a3[i][3], ap, w1.y);
                }
            }
        }
        for (int rr = 0; rr < 4; ++rr) {
            if (ksec == rr) {
#pragma unroll
                for (int i = 0; i < 4; ++i)
#pragma unroll
                    for (int j = 0; j < 4; ++j) {
                        float2 v = u2f(a3[i][j]);
                        float2* dst = (float2*)&s_h[2176 + (tokg2 * 4 + i) * 68 + cb2 + j * 2];
                        if (rr == 0) {
                            float2 bsv = *(const float2*)(bs + cb2 + j * 2);
                            *dst = make_float2(v.x + bsv.x, v.y + bsv.y);
                        } else {
                            float2 old = *dst;
                            *dst = make_float2(old.x + v.x, old.y + v.y);
                        }
                    }
            }
            __syncthreads();
        }
    }

    // ---- LN2 + shortcut -> out ----
#pragma unroll
    for (int i = 0; i < 4; ++i) {
        int tok = w * 4 + i;
        float v0 = s_z[tok * 68 + lane], v1 = s_z[tok * 68 + lane + 32];
        float s1 = v0 + v1, s2 = v0 * v0 + v1 * v1;
#pragma unroll
        for (int off = 16; off; off >>= 1) {
            s1 += __shfl_xor_sync(FULLMASK, s1, off);
            s2 += __shfl_xor_sync(FULLMASK, s2, off);
        }
        float m = s1 * (1.f / 64.f);
        float var = s2 * (1.f / 64.f) - m * m;
        float rr = rsqrtf(var + 1e-5f);
        float o0 = (v0 - m) * rr * g2[lane]      + be2[lane]      + s_h[2176 + tok * 68 + lane];
        float o1 = (v1 - m) * rr * g2[lane + 32] + be2[lane + 32] + s_h[2176 + tok * 68 + lane + 32];
        out[(base + tok) * 64 + lane]      = o0;
        out[(base + tok) * 64 + lane + 32] = o1;
    }
}

// ---------------- launch ----------------
extern "C" void kernel_launch(void* const* d_in, const int* in_sizes, int n_in,
                              void* d_out, int out_size)
{
    const float* u   = (const float*)d_in[0];
    const float* x   = (const float*)d_in[1];
    const float* Wk  = (const float*)d_in[2];
    // d_in[3] = bk: constant over u-tokens -> cancels in softmax, unused
    const float* Wq  = (const float*)d_in[4];
    const float* bq  = (const float*)d_in[5];
    const float* Wv  = (const float*)d_in[6];
    const float* bv  = (const float*)d_in[7];
    const float* g1  = (const float*)d_in[8];
    const float* be1 = (const float*)d_in[9];
    const float* Wm1 = (const float*)d_in[10];
    const float* bm1 = (const float*)d_in[11];
    const float* Wm2 = (const float*)d_in[12];
    const float* bm2 = (const float*)d_in[13];
    const float* g2  = (const float*)d_in[14];
    const float* be2 = (const float*)d_in[15];
    const float* Ws  = (const float*)d_in[16];
    const float* bs  = (const float*)d_in[17];
    float* out = (float*)d_out;

    k0_precompute<<<1, 256>>>(Wq, Wk, bq);
    fuse_all<<<Bb * TILES_PER_B, 256>>>(u, x, Wv, bv, g1, be1, Wm1, bm1,
                                        Wm2, bm2, g2, be2, Ws, bs, out);
    (void)in_sizes; (void)n_in; (void)out_size;
}